// round 5
// baseline (speedup 1.0000x reference)
#include <cuda_runtime.h>
#include <math.h>
#include <stdint.h>

#define NMAX 50000
#define EMAX 800000
#define CDIM 128
#define PADA 136   // transposed A-chunk row pad (floats)
#define PADT 132   // t-tile row pitch (floats)

// ---------------- device scratch ----------------
__device__ int   g_is64;
__device__ float g_xf [(size_t)NMAX * CDIM];
__device__ float g_agg[(size_t)NMAX * CDIM];
__device__ float g_delta[(size_t)NMAX * 3];
__device__ int   g_src [EMAX];
__device__ int   g_dst [EMAX];
__device__ int   g_esrc[EMAX];
__device__ int   g_cnt [NMAX];
__device__ int   g_cur [NMAX];
__device__ int   g_off [NMAX + 1];
__device__ int   g_bsum[64];
__device__ int   g_bpre[64];

// ---------------- f32x2 helpers ----------------
__device__ __forceinline__ unsigned long long splat2(float a) {
    unsigned long long r;
    asm("mov.b64 %0, {%1, %1};" : "=l"(r) : "f"(a));
    return r;
}
__device__ __forceinline__ void fma2(unsigned long long& d, unsigned long long a, unsigned long long b) {
    asm("fma.rn.f32x2 %0, %1, %2, %0;" : "+l"(d) : "l"(a), "l"(b));
}
__device__ __forceinline__ float2 unpk(unsigned long long v) {
    float lo, hi;
    asm("mov.b64 {%0, %1}, %2;" : "=f"(lo), "=f"(hi) : "l"(v));
    return make_float2(lo, hi);
}
__device__ __forceinline__ float lrelu(float v) { return (v > 0.f) ? v : 0.01f * v; }

// ---------------- dtype detection ----------------
__global__ void detect_kernel(const unsigned int* __restrict__ w, int E) {
    int nz = 0;
    int lim = 2 * E;
    for (int i = threadIdx.x; i < 256; i += 32) {
        int wi = 2 * i + 1;
        if (wi < lim) nz |= (w[wi] != 0u);
    }
    nz = __any_sync(0xffffffffu, nz);
    if (threadIdx.x == 0) g_is64 = nz ? 0 : 1;
}

__global__ void zero_cnt_kernel(int n) {
    int i = blockIdx.x * blockDim.x + threadIdx.x;
    if (i < n) { g_cnt[i] = 0; g_cur[i] = 0; }
}

__global__ void convert_hist_kernel(const void* __restrict__ ei, int E) {
    int i = blockIdx.x * blockDim.x + threadIdx.x;
    if (i >= E) return;
    int s, d;
    if (g_is64) {
        const long long* p = (const long long*)ei;
        s = (int)p[i];
        d = (int)p[E + i];
    } else {
        const int* p = (const int*)ei;
        s = p[i];
        d = p[E + i];
    }
    g_src[i] = s;
    g_dst[i] = d;
    atomicAdd(&g_cnt[d], 1);
}

// ---------------- hierarchical scan ----------------
__global__ void scanA_kernel(int n) {
    __shared__ int wsum[32];
    int tid = threadIdx.x, lane = tid & 31, wid = tid >> 5;
    int i = blockIdx.x * 1024 + tid;
    int v = (i < n) ? g_cnt[i] : 0;
    int x = v;
    #pragma unroll
    for (int d = 1; d < 32; d <<= 1) {
        int t = __shfl_up_sync(0xffffffffu, x, d);
        if (lane >= d) x += t;
    }
    if (lane == 31) wsum[wid] = x;
    __syncthreads();
    if (wid == 0) {
        int s = wsum[lane];
        #pragma unroll
        for (int d = 1; d < 32; d <<= 1) {
            int t = __shfl_up_sync(0xffffffffu, s, d);
            if (lane >= d) s += t;
        }
        wsum[lane] = s;
    }
    __syncthreads();
    if (wid > 0) x += wsum[wid - 1];
    if (i < n) g_off[i + 1] = x;
    if (tid == 1023) g_bsum[blockIdx.x] = x;
}

__global__ void scanB_kernel(int nb) {
    __shared__ int ws[2];
    int t = threadIdx.x, lane = t & 31, w = t >> 5;
    int v = (t < nb) ? g_bsum[t] : 0;
    int x = v;
    #pragma unroll
    for (int d = 1; d < 32; d <<= 1) {
        int u = __shfl_up_sync(0xffffffffu, x, d);
        if (lane >= d) x += u;
    }
    if (lane == 31) ws[w] = x;
    __syncthreads();
    if (w == 1) x += ws[0];
    if (t < nb) g_bpre[t] = x - v;
}

__global__ void scanC_kernel(int n) {
    int i = blockIdx.x * 1024 + threadIdx.x;
    int add = g_bpre[blockIdx.x];
    if (i < n) g_off[i + 1] += add;
    if (i == 0) g_off[0] = 0;
}

__global__ void scatter_kernel(int E) {
    int i = blockIdx.x * blockDim.x + threadIdx.x;
    if (i >= E) return;
    int d = g_dst[i];
    int p = g_off[d] + atomicAdd(&g_cur[d], 1);
    g_esrc[p] = g_src[i];
}

// ---------------- single-B GEMM core (used by out kernel) ----------------
__device__ __forceinline__ void gemm_core(
    const float* __restrict__ A, int M, int row0,
    const float* Bs, float* As, unsigned long long acc[8][4],
    int tid, int tx, int ty)
{
    int r_ = tid >> 2;
    int c_ = (tid & 3) * 4;
    int g0 = row0 + r_;
    int g1 = row0 + 64 + r_;
    const float* A0 = &A[(size_t)g0 * 128 + c_];
    const float* A1 = &A[(size_t)g1 * 128 + c_];
    bool ok0 = g0 < M, ok1 = g1 < M;

    float4 v0 = make_float4(0.f, 0.f, 0.f, 0.f);
    float4 v1 = make_float4(0.f, 0.f, 0.f, 0.f);
    if (ok0) v0 = *(const float4*)A0;
    if (ok1) v1 = *(const float4*)A1;

    #pragma unroll
    for (int k0 = 0; k0 < 128; k0 += 16) {
        As[(c_ + 0) * PADA + r_] = v0.x;
        As[(c_ + 1) * PADA + r_] = v0.y;
        As[(c_ + 2) * PADA + r_] = v0.z;
        As[(c_ + 3) * PADA + r_] = v0.w;
        As[(c_ + 0) * PADA + 64 + r_] = v1.x;
        As[(c_ + 1) * PADA + 64 + r_] = v1.y;
        As[(c_ + 2) * PADA + 64 + r_] = v1.z;
        As[(c_ + 3) * PADA + 64 + r_] = v1.w;
        if (k0 < 112) {
            v0 = make_float4(0.f, 0.f, 0.f, 0.f);
            v1 = make_float4(0.f, 0.f, 0.f, 0.f);
            if (ok0) v0 = *(const float4*)(A0 + k0 + 16);
            if (ok1) v1 = *(const float4*)(A1 + k0 + 16);
        }
        __syncthreads();
        #pragma unroll
        for (int k = 0; k < 16; k++) {
            float4 a0 = *(float4*)&As[k * PADA + ty * 8];
            float4 a1 = *(float4*)&As[k * PADA + ty * 8 + 4];
            const float* br = &Bs[(k0 + k) * 128];
            ulonglong2 b01 = *(const ulonglong2*)&br[tx * 4];
            ulonglong2 b23 = *(const ulonglong2*)&br[64 + tx * 4];
            float av[8] = {a0.x, a0.y, a0.z, a0.w, a1.x, a1.y, a1.z, a1.w};
            #pragma unroll
            for (int i = 0; i < 8; i++) {
                unsigned long long as_ = splat2(av[i]);
                fma2(acc[i][0], as_, b01.x);
                fma2(acc[i][1], as_, b01.y);
                fma2(acc[i][2], as_, b23.x);
                fma2(acc[i][3], as_, b23.y);
            }
        }
        __syncthreads();
    }
}

// ---------------- FUSED dual-B GEMM: h = x@Wh1 (-> delta) AND xf = x@WfX + bf ----------------
// Shares A-tile staging between both GEMMs: smem crossbar bytes per FFMA2 drop
// from 2.0 to 1.5 (A read feeds 64 FFMA2 instead of 32).
__global__ __launch_bounds__(256, 1)
void gemm_dual_kernel(const float* __restrict__ A,
                      const float* __restrict__ W1, const float* __restrict__ b1,   // Wh1, bh1
                      const float* __restrict__ Wh2, const float* __restrict__ bh2,
                      const float* __restrict__ W2, const float* __restrict__ b2,   // WfX, bf
                      int M) {
    extern __shared__ float sm[];
    float* Bs1  = sm;                   // 16384
    float* Bs2  = sm + 16384;           // 16384
    float* As   = sm + 32768;           // 16*PADA = 2176
    float* sW2  = As + 16 * PADA;       // 384
    float* sdel = sW2 + 384;            // 384
    int tid = threadIdx.x, tx = tid & 15, ty = tid >> 4;
    int row0 = blockIdx.x * 128;

    #pragma unroll
    for (int it = 0; it < 16; ++it) {
        int idx = (it * 256 + tid) * 4;
        *(float4*)&Bs1[idx] = *(const float4*)&W1[idx];
        *(float4*)&Bs2[idx] = *(const float4*)&W2[idx];
    }
    if (tid < 96) *(float4*)&sW2[tid * 4] = *(const float4*)&Wh2[tid * 4];

    unsigned long long acc1[8][4], acc2[8][4];
    #pragma unroll
    for (int i = 0; i < 8; i++)
        #pragma unroll
        for (int j = 0; j < 4; j++) { acc1[i][j] = 0ull; acc2[i][j] = 0ull; }

    // A staging with register prefetch (same pipeline as gemm_core)
    {
        int r_ = tid >> 2;
        int c_ = (tid & 3) * 4;
        int g0 = row0 + r_;
        int g1 = row0 + 64 + r_;
        const float* A0 = &A[(size_t)g0 * 128 + c_];
        const float* A1 = &A[(size_t)g1 * 128 + c_];
        bool ok0 = g0 < M, ok1 = g1 < M;

        float4 v0 = make_float4(0.f, 0.f, 0.f, 0.f);
        float4 v1 = make_float4(0.f, 0.f, 0.f, 0.f);
        if (ok0) v0 = *(const float4*)A0;
        if (ok1) v1 = *(const float4*)A1;

        #pragma unroll
        for (int k0 = 0; k0 < 128; k0 += 16) {
            As[(c_ + 0) * PADA + r_] = v0.x;
            As[(c_ + 1) * PADA + r_] = v0.y;
            As[(c_ + 2) * PADA + r_] = v0.z;
            As[(c_ + 3) * PADA + r_] = v0.w;
            As[(c_ + 0) * PADA + 64 + r_] = v1.x;
            As[(c_ + 1) * PADA + 64 + r_] = v1.y;
            As[(c_ + 2) * PADA + 64 + r_] = v1.z;
            As[(c_ + 3) * PADA + 64 + r_] = v1.w;
            if (k0 < 112) {
                v0 = make_float4(0.f, 0.f, 0.f, 0.f);
                v1 = make_float4(0.f, 0.f, 0.f, 0.f);
                if (ok0) v0 = *(const float4*)(A0 + k0 + 16);
                if (ok1) v1 = *(const float4*)(A1 + k0 + 16);
            }
            __syncthreads();
            #pragma unroll
            for (int k = 0; k < 16; k++) {
                float4 a0 = *(float4*)&As[k * PADA + ty * 8];
                float4 a1 = *(float4*)&As[k * PADA + ty * 8 + 4];
                const float* br1 = &Bs1[(k0 + k) * 128];
                const float* br2 = &Bs2[(k0 + k) * 128];
                ulonglong2 p01 = *(const ulonglong2*)&br1[tx * 4];
                ulonglong2 p23 = *(const ulonglong2*)&br1[64 + tx * 4];
                ulonglong2 q01 = *(const ulonglong2*)&br2[tx * 4];
                ulonglong2 q23 = *(const ulonglong2*)&br2[64 + tx * 4];
                float av[8] = {a0.x, a0.y, a0.z, a0.w, a1.x, a1.y, a1.z, a1.w};
                #pragma unroll
                for (int i = 0; i < 8; i++) {
                    unsigned long long as_ = splat2(av[i]);
                    fma2(acc1[i][0], as_, p01.x);
                    fma2(acc1[i][1], as_, p01.y);
                    fma2(acc1[i][2], as_, p23.x);
                    fma2(acc1[i][3], as_, p23.y);
                    fma2(acc2[i][0], as_, q01.x);
                    fma2(acc2[i][1], as_, q01.y);
                    fma2(acc2[i][2], as_, q23.x);
                    fma2(acc2[i][3], as_, q23.y);
                }
            }
            __syncthreads();
        }
    }

    // epilogue A: xf = acc2 + bf -> g_xf
    {
        float4 bA = *(const float4*)&b2[tx * 4];
        float4 bB = *(const float4*)&b2[64 + tx * 4];
        #pragma unroll
        for (int i = 0; i < 8; i++) {
            int grow = row0 + ty * 8 + i;
            if (grow >= M) continue;
            float2 f0 = unpk(acc2[i][0]), f1 = unpk(acc2[i][1]);
            float2 f2 = unpk(acc2[i][2]), f3 = unpk(acc2[i][3]);
            *(float4*)&g_xf[(size_t)grow * 128 + tx * 4] =
                make_float4(f0.x + bA.x, f0.y + bA.y, f1.x + bA.z, f1.y + bA.w);
            *(float4*)&g_xf[(size_t)grow * 128 + 64 + tx * 4] =
                make_float4(f2.x + bB.x, f2.y + bB.y, f3.x + bB.z, f3.y + bB.w);
        }
    }

    // epilogue B: delta = tanh(lrelu(acc1 + bh1) @ Wh2 + bh2)
    {
        float4 bA = *(const float4*)&b1[tx * 4];
        float4 bB = *(const float4*)&b1[64 + tx * 4];
        float bb[8] = {bA.x, bA.y, bA.z, bA.w, bB.x, bB.y, bB.z, bB.w};
        #pragma unroll
        for (int i = 0; i < 8; i++) {
            float p0 = 0.f, p1 = 0.f, p2 = 0.f;
            #pragma unroll
            for (int j = 0; j < 4; j++) {
                int c0 = (j < 2) ? (tx * 4 + j * 2) : (64 + tx * 4 + (j - 2) * 2);
                float2 f = unpk(acc1[i][j]);
                f.x = lrelu(f.x + bb[j * 2 + 0]);
                f.y = lrelu(f.y + bb[j * 2 + 1]);
                p0 += f.x * sW2[c0 * 3 + 0] + f.y * sW2[(c0 + 1) * 3 + 0];
                p1 += f.x * sW2[c0 * 3 + 1] + f.y * sW2[(c0 + 1) * 3 + 1];
                p2 += f.x * sW2[c0 * 3 + 2] + f.y * sW2[(c0 + 1) * 3 + 2];
            }
            #pragma unroll
            for (int d = 1; d < 16; d <<= 1) {
                p0 += __shfl_xor_sync(0xffffffffu, p0, d);
                p1 += __shfl_xor_sync(0xffffffffu, p1, d);
                p2 += __shfl_xor_sync(0xffffffffu, p2, d);
            }
            if (tx == 0) {
                int r = ty * 8 + i;
                sdel[r * 3 + 0] = p0;
                sdel[r * 3 + 1] = p1;
                sdel[r * 3 + 2] = p2;
            }
        }
        __syncthreads();
        if (tid < 128) {
            int grow = row0 + tid;
            if (grow < M) {
                g_delta[grow * 3 + 0] = tanhf(sdel[tid * 3 + 0] + bh2[0]);
                g_delta[grow * 3 + 1] = tanhf(sdel[tid * 3 + 1] + bh2[1]);
                g_delta[grow * 3 + 2] = tanhf(sdel[tid * 3 + 2] + bh2[2]);
            }
        }
    }
}

// ---------------- edge aggregation: warp per dst node ----------------
__global__ void agg_kernel(const float* __restrict__ pos, const float* __restrict__ Wf, int N) {
    int warp = (blockIdx.x * blockDim.x + threadIdx.x) >> 5;
    int lane = threadIdx.x & 31;
    if (warp >= N) return;
    int c = lane * 4;
    float4 w0 = *(const float4*)&Wf[c];
    float4 w1 = *(const float4*)&Wf[128 + c];
    float4 w2 = *(const float4*)&Wf[256 + c];
    float bx = g_delta[warp * 3 + 0] - pos[warp * 3 + 0];
    float by = g_delta[warp * 3 + 1] - pos[warp * 3 + 1];
    float bz = g_delta[warp * 3 + 2] - pos[warp * 3 + 2];
    int p0 = g_off[warp], p1 = g_off[warp + 1];
    float4 acc = make_float4(-INFINITY, -INFINITY, -INFINITY, -INFINITY);
    int p = p0;
    for (; p + 2 <= p1; p += 2) {
        int s0 = g_esrc[p], s1 = g_esrc[p + 1];
        float rx0 = pos[s0 * 3 + 0] + bx, ry0 = pos[s0 * 3 + 1] + by, rz0 = pos[s0 * 3 + 2] + bz;
        float rx1 = pos[s1 * 3 + 0] + bx, ry1 = pos[s1 * 3 + 1] + by, rz1 = pos[s1 * 3 + 2] + bz;
        float4 v0 = *(const float4*)&g_xf[(size_t)s0 * 128 + c];
        float4 v1 = *(const float4*)&g_xf[(size_t)s1 * 128 + c];
        acc.x = fmaxf(acc.x, fmaf(rz0, w2.x, fmaf(ry0, w1.x, fmaf(rx0, w0.x, v0.x))));
        acc.y = fmaxf(acc.y, fmaf(rz0, w2.y, fmaf(ry0, w1.y, fmaf(rx0, w0.y, v0.y))));
        acc.z = fmaxf(acc.z, fmaf(rz0, w2.z, fmaf(ry0, w1.z, fmaf(rx0, w0.z, v0.z))));
        acc.w = fmaxf(acc.w, fmaf(rz0, w2.w, fmaf(ry0, w1.w, fmaf(rx0, w0.w, v0.w))));
        acc.x = fmaxf(acc.x, fmaf(rz1, w2.x, fmaf(ry1, w1.x, fmaf(rx1, w0.x, v1.x))));
        acc.y = fmaxf(acc.y, fmaf(rz1, w2.y, fmaf(ry1, w1.y, fmaf(rx1, w0.y, v1.y))));
        acc.z = fmaxf(acc.z, fmaf(rz1, w2.z, fmaf(ry1, w1.z, fmaf(rx1, w0.z, v1.z))));
        acc.w = fmaxf(acc.w, fmaf(rz1, w2.w, fmaf(ry1, w1.w, fmaf(rx1, w0.w, v1.w))));
    }
    if (p < p1) {
        int s = g_esrc[p];
        float rx = pos[s * 3 + 0] + bx, ry = pos[s * 3 + 1] + by, rz = pos[s * 3 + 2] + bz;
        float4 v = *(const float4*)&g_xf[(size_t)s * 128 + c];
        acc.x = fmaxf(acc.x, fmaf(rz, w2.x, fmaf(ry, w1.x, fmaf(rx, w0.x, v.x))));
        acc.y = fmaxf(acc.y, fmaf(rz, w2.y, fmaf(ry, w1.y, fmaf(rx, w0.y, v.y))));
        acc.z = fmaxf(acc.z, fmaf(rz, w2.z, fmaf(ry, w1.z, fmaf(rx, w0.z, v.z))));
        acc.w = fmaxf(acc.w, fmaf(rz, w2.w, fmaf(ry, w1.w, fmaf(rx, w0.w, v.w))));
    }
    float4 o;
    if (p1 > p0) {
        o.x = lrelu(acc.x); o.y = lrelu(acc.y);
        o.z = lrelu(acc.z); o.w = lrelu(acc.w);
    } else {
        o = make_float4(0.f, 0.f, 0.f, 0.f);
    }
    *(float4*)&g_agg[(size_t)warp * 128 + c] = o;
}

// ---------------- fused: out = lrelu(agg@Wg1+bg1)@Wg2 + bg2 + x ----------------
__global__ __launch_bounds__(256, 1)
void gemm_out_kernel(const float* __restrict__ A, const float* __restrict__ B1,
                     const float* __restrict__ b1, const float* __restrict__ B2,
                     const float* __restrict__ b2, const float* __restrict__ X,
                     float* __restrict__ O, int M) {
    extern __shared__ float sm[];
    float* Bs1 = sm;                       // 16384
    float* Bs2 = sm + 16384;               // 16384
    float* Ts  = sm + 32768;               // 128*PADT
    float* As  = sm + 32768 + 16896;       // 16*PADA
    int tid = threadIdx.x, tx = tid & 15, ty = tid >> 4;
    int row0 = blockIdx.x * 128;

    #pragma unroll
    for (int it = 0; it < 16; ++it) {
        int idx = (it * 256 + tid) * 4;
        *(float4*)&Bs1[idx] = *(const float4*)&B1[idx];
        *(float4*)&Bs2[idx] = *(const float4*)&B2[idx];
    }
    unsigned long long acc[8][4];
    #pragma unroll
    for (int i = 0; i < 8; i++)
        #pragma unroll
        for (int j = 0; j < 4; j++) acc[i][j] = 0ull;

    gemm_core(A, M, row0, Bs1, As, acc, tid, tx, ty);

    {
        float4 bA = *(const float4*)&b1[tx * 4];
        float4 bB = *(const float4*)&b1[64 + tx * 4];
        #pragma unroll
        for (int i = 0; i < 8; i++) {
            int r = ty * 8 + i;
            float2 f0 = unpk(acc[i][0]), f1 = unpk(acc[i][1]);
            float2 f2 = unpk(acc[i][2]), f3 = unpk(acc[i][3]);
            *(float4*)&Ts[r * PADT + tx * 4] =
                make_float4(lrelu(f0.x + bA.x), lrelu(f0.y + bA.y),
                            lrelu(f1.x + bA.z), lrelu(f1.y + bA.w));
            *(float4*)&Ts[r * PADT + 64 + tx * 4] =
                make_float4(lrelu(f2.x + bB.x), lrelu(f2.y + bB.y),
                            lrelu(f3.x + bB.z), lrelu(f3.y + bB.w));
        }
    }
    __syncthreads();

    #pragma unroll
    for (int i = 0; i < 8; i++)
        #pragma unroll
        for (int j = 0; j < 4; j++) acc[i][j] = 0ull;

    #pragma unroll 4
    for (int k = 0; k < 128; k++) {
        const float* br = &Bs2[k * 128];
        ulonglong2 b01 = *(const ulonglong2*)&br[tx * 4];
        ulonglong2 b23 = *(const ulonglong2*)&br[64 + tx * 4];
        #pragma unroll
        for (int i = 0; i < 8; i++) {
            unsigned long long as_ = splat2(Ts[(ty * 8 + i) * PADT + k]);
            fma2(acc[i][0], as_, b01.x);
            fma2(acc[i][1], as_, b01.y);
            fma2(acc[i][2], as_, b23.x);
            fma2(acc[i][3], as_, b23.y);
        }
    }

    float4 bA = *(const float4*)&b2[tx * 4];
    float4 bB = *(const float4*)&b2[64 + tx * 4];
    #pragma unroll
    for (int i = 0; i < 8; i++) {
        int grow = row0 + ty * 8 + i;
        if (grow >= M) continue;
        float2 f0 = unpk(acc[i][0]), f1 = unpk(acc[i][1]);
        float2 f2 = unpk(acc[i][2]), f3 = unpk(acc[i][3]);
        float4 r0 = *(const float4*)&X[(size_t)grow * 128 + tx * 4];
        float4 r1 = *(const float4*)&X[(size_t)grow * 128 + 64 + tx * 4];
        *(float4*)&O[(size_t)grow * 128 + tx * 4] =
            make_float4(f0.x + bA.x + r0.x, f0.y + bA.y + r0.y,
                        f1.x + bA.z + r0.z, f1.y + bA.w + r0.w);
        *(float4*)&O[(size_t)grow * 128 + 64 + tx * 4] =
            make_float4(f2.x + bB.x + r1.x, f2.y + bB.y + r1.y,
                        f3.x + bB.z + r1.z, f3.y + bB.w + r1.w);
    }
}

// ---------------- launch ----------------
extern "C" void kernel_launch(void* const* d_in, const int* in_sizes, int n_in,
                              void* d_out, int out_size) {
    const float* x   = (const float*)d_in[0];
    const float* pos = (const float*)d_in[1];
    const void*  ei  = d_in[2];
    const float* Wh1 = (const float*)d_in[3];
    const float* bh1 = (const float*)d_in[4];
    const float* Wh2 = (const float*)d_in[5];
    const float* bh2 = (const float*)d_in[6];
    const float* Wf  = (const float*)d_in[7];
    const float* bf  = (const float*)d_in[8];
    const float* Wg1 = (const float*)d_in[9];
    const float* bg1 = (const float*)d_in[10];
    const float* Wg2 = (const float*)d_in[11];
    const float* bg2 = (const float*)d_in[12];
    float* out = (float*)d_out;

    int M = in_sizes[0] / CDIM;   // 50000
    int E = in_sizes[2] / 2;      // 800000

    const int SM_DUAL = (16384 * 2 + 16 * PADA + 384 + 384) * sizeof(float);
    const int SM_OUT  = (16384 * 2 + 128 * PADT + 16 * PADA) * sizeof(float);
    cudaFuncSetAttribute(gemm_dual_kernel, cudaFuncAttributeMaxDynamicSharedMemorySize, SM_DUAL);
    cudaFuncSetAttribute(gemm_out_kernel,  cudaFuncAttributeMaxDynamicSharedMemorySize, SM_OUT);

    float* aggp;
    cudaGetSymbolAddress((void**)&aggp, g_agg);

    int gemm_blocks = (M + 127) / 128;
    int eblocks = (E + 255) / 256;
    int nblocks = (M + 255) / 256;
    int sblocks = (M + 1023) / 1024;
    int wblocks = (M + 7) / 8;

    static cudaStream_t s_side = nullptr;
    static cudaEvent_t  s_e0 = nullptr, s_e1 = nullptr;
    if (s_side == nullptr) {
        cudaStreamCreateWithFlags(&s_side, cudaStreamNonBlocking);
        cudaEventCreateWithFlags(&s_e0, cudaEventDisableTiming);
        cudaEventCreateWithFlags(&s_e1, cudaEventDisableTiming);
    }

    // fork: CSR build on side stream
    cudaEventRecord(s_e0, 0);
    cudaStreamWaitEvent(s_side, s_e0, 0);
    detect_kernel<<<1, 32, 0, s_side>>>((const unsigned int*)ei, E);
    zero_cnt_kernel<<<nblocks, 256, 0, s_side>>>(M);
    convert_hist_kernel<<<eblocks, 256, 0, s_side>>>(ei, E);
    scanA_kernel<<<sblocks, 1024, 0, s_side>>>(M);
    scanB_kernel<<<1, 64, 0, s_side>>>(sblocks);
    scanC_kernel<<<sblocks, 1024, 0, s_side>>>(M);
    scatter_kernel<<<eblocks, 256, 0, s_side>>>(E);
    cudaEventRecord(s_e1, s_side);

    // main stream: fused dual GEMM (hdelta + xf share the A tile)
    gemm_dual_kernel<<<gemm_blocks, 256, SM_DUAL>>>(x, Wh1, bh1, Wh2, bh2, Wf + 3 * 128, bf, M);

    // join, then aggregate + output MLP
    cudaStreamWaitEvent(0, s_e1, 0);
    agg_kernel<<<wblocks, 256>>>(pos, Wf, M);
    gemm_out_kernel<<<gemm_blocks, 256, SM_OUT>>>(aggp, Wg1, bg1, Wg2, bg2, x, out, M);
}

// round 6
// speedup vs baseline: 1.0933x; 1.0933x over previous
#include <cuda_runtime.h>
#include <math.h>
#include <stdint.h>

#define NMAX 50000
#define EMAX 800000
#define CDIM 128
#define PADA 136   // transposed A-chunk row pad (floats)
#define PADT 132   // t-tile row pitch (floats)

// ---------------- device scratch ----------------
__device__ int    g_is64;
__device__ float  g_xf [(size_t)NMAX * CDIM];
__device__ float  g_agg[(size_t)NMAX * CDIM];
__device__ float  g_delta[(size_t)NMAX * 3];
__device__ int    g_src [EMAX];
__device__ int    g_dst [EMAX];
__device__ float4 g_epay[EMAX];   // per-edge payload grouped by dst: (pos_src.xyz, src-bits)
__device__ int    g_cnt [NMAX];
__device__ int    g_cur [NMAX];
__device__ int    g_off [NMAX + 1];
__device__ int    g_bsum[64];
__device__ int    g_bpre[64];

// ---------------- f32x2 helpers ----------------
__device__ __forceinline__ unsigned long long splat2(float a) {
    unsigned long long r;
    asm("mov.b64 %0, {%1, %1};" : "=l"(r) : "f"(a));
    return r;
}
__device__ __forceinline__ void fma2(unsigned long long& d, unsigned long long a, unsigned long long b) {
    asm("fma.rn.f32x2 %0, %1, %2, %0;" : "+l"(d) : "l"(a), "l"(b));
}
__device__ __forceinline__ float2 unpk(unsigned long long v) {
    float lo, hi;
    asm("mov.b64 {%0, %1}, %2;" : "=f"(lo), "=f"(hi) : "l"(v));
    return make_float2(lo, hi);
}
__device__ __forceinline__ float lrelu(float v) { return (v > 0.f) ? v : 0.01f * v; }

// ---------------- dtype detection ----------------
__global__ void detect_kernel(const unsigned int* __restrict__ w, int E) {
    int nz = 0;
    int lim = 2 * E;
    for (int i = threadIdx.x; i < 256; i += 32) {
        int wi = 2 * i + 1;
        if (wi < lim) nz |= (w[wi] != 0u);
    }
    nz = __any_sync(0xffffffffu, nz);
    if (threadIdx.x == 0) g_is64 = nz ? 0 : 1;
}

__global__ void zero_cnt_kernel(int n) {
    int i = blockIdx.x * blockDim.x + threadIdx.x;
    if (i < n) { g_cnt[i] = 0; g_cur[i] = 0; }
}

__global__ void convert_hist_kernel(const void* __restrict__ ei, int E) {
    int i = blockIdx.x * blockDim.x + threadIdx.x;
    if (i >= E) return;
    int s, d;
    if (g_is64) {
        const long long* p = (const long long*)ei;
        s = (int)p[i];
        d = (int)p[E + i];
    } else {
        const int* p = (const int*)ei;
        s = p[i];
        d = p[E + i];
    }
    g_src[i] = s;
    g_dst[i] = d;
    atomicAdd(&g_cnt[d], 1);
}

// ---------------- hierarchical scan ----------------
__global__ void scanA_kernel(int n) {
    __shared__ int wsum[32];
    int tid = threadIdx.x, lane = tid & 31, wid = tid >> 5;
    int i = blockIdx.x * 1024 + tid;
    int v = (i < n) ? g_cnt[i] : 0;
    int x = v;
    #pragma unroll
    for (int d = 1; d < 32; d <<= 1) {
        int t = __shfl_up_sync(0xffffffffu, x, d);
        if (lane >= d) x += t;
    }
    if (lane == 31) wsum[wid] = x;
    __syncthreads();
    if (wid == 0) {
        int s = wsum[lane];
        #pragma unroll
        for (int d = 1; d < 32; d <<= 1) {
            int t = __shfl_up_sync(0xffffffffu, s, d);
            if (lane >= d) s += t;
        }
        wsum[lane] = s;
    }
    __syncthreads();
    if (wid > 0) x += wsum[wid - 1];
    if (i < n) g_off[i + 1] = x;
    if (tid == 1023) g_bsum[blockIdx.x] = x;
}

__global__ void scanB_kernel(int nb) {
    __shared__ int ws[2];
    int t = threadIdx.x, lane = t & 31, w = t >> 5;
    int v = (t < nb) ? g_bsum[t] : 0;
    int x = v;
    #pragma unroll
    for (int d = 1; d < 32; d <<= 1) {
        int u = __shfl_up_sync(0xffffffffu, x, d);
        if (lane >= d) x += u;
    }
    if (lane == 31) ws[w] = x;
    __syncthreads();
    if (w == 1) x += ws[0];
    if (t < nb) g_bpre[t] = x - v;
}

__global__ void scanC_kernel(int n) {
    int i = blockIdx.x * 1024 + threadIdx.x;
    int add = g_bpre[blockIdx.x];
    if (i < n) g_off[i + 1] += add;
    if (i == 0) g_off[0] = 0;
}

// scatter edges grouped by dst; pack (pos[src], src) into one float4 payload
__global__ void scatter_kernel(const float* __restrict__ pos, int E) {
    int i = blockIdx.x * blockDim.x + threadIdx.x;
    if (i >= E) return;
    int d = g_dst[i];
    int s = g_src[i];
    int p = g_off[d] + atomicAdd(&g_cur[d], 1);
    g_epay[p] = make_float4(pos[s * 3 + 0], pos[s * 3 + 1], pos[s * 3 + 2], __int_as_float(s));
}

// ---------------- GEMM core with register-prefetch pipeline ----------------
__device__ __forceinline__ void gemm_core(
    const float* __restrict__ A, int M, int row0,
    const float* Bs, float* As, unsigned long long acc[8][4],
    int tid, int tx, int ty)
{
    int r_ = tid >> 2;
    int c_ = (tid & 3) * 4;
    int g0 = row0 + r_;
    int g1 = row0 + 64 + r_;
    const float* A0 = &A[(size_t)g0 * 128 + c_];
    const float* A1 = &A[(size_t)g1 * 128 + c_];
    bool ok0 = g0 < M, ok1 = g1 < M;

    float4 v0 = make_float4(0.f, 0.f, 0.f, 0.f);
    float4 v1 = make_float4(0.f, 0.f, 0.f, 0.f);
    if (ok0) v0 = *(const float4*)A0;
    if (ok1) v1 = *(const float4*)A1;

    #pragma unroll
    for (int k0 = 0; k0 < 128; k0 += 16) {
        As[(c_ + 0) * PADA + r_] = v0.x;
        As[(c_ + 1) * PADA + r_] = v0.y;
        As[(c_ + 2) * PADA + r_] = v0.z;
        As[(c_ + 3) * PADA + r_] = v0.w;
        As[(c_ + 0) * PADA + 64 + r_] = v1.x;
        As[(c_ + 1) * PADA + 64 + r_] = v1.y;
        As[(c_ + 2) * PADA + 64 + r_] = v1.z;
        As[(c_ + 3) * PADA + 64 + r_] = v1.w;
        if (k0 < 112) {
            v0 = make_float4(0.f, 0.f, 0.f, 0.f);
            v1 = make_float4(0.f, 0.f, 0.f, 0.f);
            if (ok0) v0 = *(const float4*)(A0 + k0 + 16);
            if (ok1) v1 = *(const float4*)(A1 + k0 + 16);
        }
        __syncthreads();
        #pragma unroll
        for (int k = 0; k < 16; k++) {
            float4 a0 = *(float4*)&As[k * PADA + ty * 8];
            float4 a1 = *(float4*)&As[k * PADA + ty * 8 + 4];
            const float* br = &Bs[(k0 + k) * 128];
            ulonglong2 b01 = *(const ulonglong2*)&br[tx * 4];
            ulonglong2 b23 = *(const ulonglong2*)&br[64 + tx * 4];
            float av[8] = {a0.x, a0.y, a0.z, a0.w, a1.x, a1.y, a1.z, a1.w};
            #pragma unroll
            for (int i = 0; i < 8; i++) {
                unsigned long long as_ = splat2(av[i]);
                fma2(acc[i][0], as_, b01.x);
                fma2(acc[i][1], as_, b01.y);
                fma2(acc[i][2], as_, b23.x);
                fma2(acc[i][3], as_, b23.y);
            }
        }
        __syncthreads();
    }
}

// ---------------- xf = x @ Wf_x + bf ----------------
__global__ __launch_bounds__(256, 2)
void gemm_bias_kernel(const float* __restrict__ A, const float* __restrict__ B,
                      const float* __restrict__ bias, float* __restrict__ O, int M) {
    extern __shared__ float sm[];
    float* Bs = sm;
    float* As = sm + 16384;
    int tid = threadIdx.x, tx = tid & 15, ty = tid >> 4;
    int row0 = blockIdx.x * 128;

    #pragma unroll
    for (int it = 0; it < 16; ++it) {
        int idx = (it * 256 + tid) * 4;
        *(float4*)&Bs[idx] = *(const float4*)&B[idx];
    }
    unsigned long long acc[8][4];
    #pragma unroll
    for (int i = 0; i < 8; i++)
        #pragma unroll
        for (int j = 0; j < 4; j++) acc[i][j] = 0ull;

    gemm_core(A, M, row0, Bs, As, acc, tid, tx, ty);

    float4 bA = *(const float4*)&bias[tx * 4];
    float4 bB = *(const float4*)&bias[64 + tx * 4];
    #pragma unroll
    for (int i = 0; i < 8; i++) {
        int grow = row0 + ty * 8 + i;
        if (grow >= M) continue;
        float2 f0 = unpk(acc[i][0]), f1 = unpk(acc[i][1]);
        float2 f2 = unpk(acc[i][2]), f3 = unpk(acc[i][3]);
        *(float4*)&O[(size_t)grow * 128 + tx * 4] =
            make_float4(f0.x + bA.x, f0.y + bA.y, f1.x + bA.z, f1.y + bA.w);
        *(float4*)&O[(size_t)grow * 128 + 64 + tx * 4] =
            make_float4(f2.x + bB.x, f2.y + bB.y, f3.x + bB.z, f3.y + bB.w);
    }
}

// ---------------- delta = tanh(lrelu(x@Wh1+bh1) @ Wh2 + bh2), fused ----------------
__global__ __launch_bounds__(256, 2)
void gemm_hdelta_kernel(const float* __restrict__ A, const float* __restrict__ B,
                        const float* __restrict__ bias,
                        const float* __restrict__ Wh2, const float* __restrict__ bh2, int M) {
    extern __shared__ float sm[];
    float* Bs   = sm;
    float* As   = sm + 16384;
    float* sW2  = sm + 16384 + 2176;
    float* sdel = sm + 16384 + 2176 + 384;
    int tid = threadIdx.x, tx = tid & 15, ty = tid >> 4;
    int row0 = blockIdx.x * 128;

    #pragma unroll
    for (int it = 0; it < 16; ++it) {
        int idx = (it * 256 + tid) * 4;
        *(float4*)&Bs[idx] = *(const float4*)&B[idx];
    }
    if (tid < 96) *(float4*)&sW2[tid * 4] = *(const float4*)&Wh2[tid * 4];

    unsigned long long acc[8][4];
    #pragma unroll
    for (int i = 0; i < 8; i++)
        #pragma unroll
        for (int j = 0; j < 4; j++) acc[i][j] = 0ull;

    gemm_core(A, M, row0, Bs, As, acc, tid, tx, ty);

    float4 bA = *(const float4*)&bias[tx * 4];
    float4 bB = *(const float4*)&bias[64 + tx * 4];
    float bb[8] = {bA.x, bA.y, bA.z, bA.w, bB.x, bB.y, bB.z, bB.w};

    #pragma unroll
    for (int i = 0; i < 8; i++) {
        float p0 = 0.f, p1 = 0.f, p2 = 0.f;
        #pragma unroll
        for (int j = 0; j < 4; j++) {
            int c0 = (j < 2) ? (tx * 4 + j * 2) : (64 + tx * 4 + (j - 2) * 2);
            float2 f = unpk(acc[i][j]);
            f.x = lrelu(f.x + bb[j * 2 + 0]);
            f.y = lrelu(f.y + bb[j * 2 + 1]);
            p0 += f.x * sW2[c0 * 3 + 0] + f.y * sW2[(c0 + 1) * 3 + 0];
            p1 += f.x * sW2[c0 * 3 + 1] + f.y * sW2[(c0 + 1) * 3 + 1];
            p2 += f.x * sW2[c0 * 3 + 2] + f.y * sW2[(c0 + 1) * 3 + 2];
        }
        #pragma unroll
        for (int d = 1; d < 16; d <<= 1) {
            p0 += __shfl_xor_sync(0xffffffffu, p0, d);
            p1 += __shfl_xor_sync(0xffffffffu, p1, d);
            p2 += __shfl_xor_sync(0xffffffffu, p2, d);
        }
        if (tx == 0) {
            int r = ty * 8 + i;
            sdel[r * 3 + 0] = p0;
            sdel[r * 3 + 1] = p1;
            sdel[r * 3 + 2] = p2;
        }
    }
    __syncthreads();
    if (tid < 128) {
        int grow = row0 + tid;
        if (grow < M) {
            g_delta[grow * 3 + 0] = tanhf(sdel[tid * 3 + 0] + bh2[0]);
            g_delta[grow * 3 + 1] = tanhf(sdel[tid * 3 + 1] + bh2[1]);
            g_delta[grow * 3 + 2] = tanhf(sdel[tid * 3 + 2] + bh2[2]);
        }
    }
}

// ---------------- edge aggregation: warp per dst node, packed payload ----------------
__global__ void agg_kernel(const float* __restrict__ pos, const float* __restrict__ Wf, int N) {
    int warp = (blockIdx.x * blockDim.x + threadIdx.x) >> 5;
    int lane = threadIdx.x & 31;
    if (warp >= N) return;
    int c = lane * 4;
    float4 w0 = *(const float4*)&Wf[c];
    float4 w1 = *(const float4*)&Wf[128 + c];
    float4 w2 = *(const float4*)&Wf[256 + c];
    float bx = g_delta[warp * 3 + 0] - pos[warp * 3 + 0];
    float by = g_delta[warp * 3 + 1] - pos[warp * 3 + 1];
    float bz = g_delta[warp * 3 + 2] - pos[warp * 3 + 2];
    int p0 = g_off[warp], p1 = g_off[warp + 1];
    float4 acc = make_float4(-INFINITY, -INFINITY, -INFINITY, -INFINITY);
    int p = p0;
    for (; p + 2 <= p1; p += 2) {
        float4 e0 = g_epay[p];
        float4 e1 = g_epay[p + 1];
        int s0 = __float_as_int(e0.w), s1 = __float_as_int(e1.w);
        float4 v0 = *(const float4*)&g_xf[(size_t)s0 * 128 + c];
        float4 v1 = *(const float4*)&g_xf[(size_t)s1 * 128 + c];
        float rx0 = e0.x + bx, ry0 = e0.y + by, rz0 = e0.z + bz;
        float rx1 = e1.x + bx, ry1 = e1.y + by, rz1 = e1.z + bz;
        acc.x = fmaxf(acc.x, fmaf(rz0, w2.x, fmaf(ry0, w1.x, fmaf(rx0, w0.x, v0.x))));
        acc.y = fmaxf(acc.y, fmaf(rz0, w2.y, fmaf(ry0, w1.y, fmaf(rx0, w0.y, v0.y))));
        acc.z = fmaxf(acc.z, fmaf(rz0, w2.z, fmaf(ry0, w1.z, fmaf(rx0, w0.z, v0.z))));
        acc.w = fmaxf(acc.w, fmaf(rz0, w2.w, fmaf(ry0, w1.w, fmaf(rx0, w0.w, v0.w))));
        acc.x = fmaxf(acc.x, fmaf(rz1, w2.x, fmaf(ry1, w1.x, fmaf(rx1, w0.x, v1.x))));
        acc.y = fmaxf(acc.y, fmaf(rz1, w2.y, fmaf(ry1, w1.y, fmaf(rx1, w0.y, v1.y))));
        acc.z = fmaxf(acc.z, fmaf(rz1, w2.z, fmaf(ry1, w1.z, fmaf(rx1, w0.z, v1.z))));
        acc.w = fmaxf(acc.w, fmaf(rz1, w2.w, fmaf(ry1, w1.w, fmaf(rx1, w0.w, v1.w))));
    }
    if (p < p1) {
        float4 e = g_epay[p];
        int s = __float_as_int(e.w);
        float4 v = *(const float4*)&g_xf[(size_t)s * 128 + c];
        float rx = e.x + bx, ry = e.y + by, rz = e.z + bz;
        acc.x = fmaxf(acc.x, fmaf(rz, w2.x, fmaf(ry, w1.x, fmaf(rx, w0.x, v.x))));
        acc.y = fmaxf(acc.y, fmaf(rz, w2.y, fmaf(ry, w1.y, fmaf(rx, w0.y, v.y))));
        acc.z = fmaxf(acc.z, fmaf(rz, w2.z, fmaf(ry, w1.z, fmaf(rx, w0.z, v.z))));
        acc.w = fmaxf(acc.w, fmaf(rz, w2.w, fmaf(ry, w1.w, fmaf(rx, w0.w, v.w))));
    }
    float4 o;
    if (p1 > p0) {
        o.x = lrelu(acc.x); o.y = lrelu(acc.y);
        o.z = lrelu(acc.z); o.w = lrelu(acc.w);
    } else {
        o = make_float4(0.f, 0.f, 0.f, 0.f);
    }
    *(float4*)&g_agg[(size_t)warp * 128 + c] = o;
}

// ---------------- fused: out = lrelu(agg@Wg1+bg1)@Wg2 + bg2 + x ----------------
__global__ __launch_bounds__(256, 1)
void gemm_out_kernel(const float* __restrict__ A, const float* __restrict__ B1,
                     const float* __restrict__ b1, const float* __restrict__ B2,
                     const float* __restrict__ b2, const float* __restrict__ X,
                     float* __restrict__ O, int M) {
    extern __shared__ float sm[];
    float* Bs1 = sm;
    float* Bs2 = sm + 16384;
    float* Ts  = sm + 32768;
    float* As  = sm + 32768 + 16896;
    int tid = threadIdx.x, tx = tid & 15, ty = tid >> 4;
    int row0 = blockIdx.x * 128;

    #pragma unroll
    for (int it = 0; it < 16; ++it) {
        int idx = (it * 256 + tid) * 4;
        *(float4*)&Bs1[idx] = *(const float4*)&B1[idx];
        *(float4*)&Bs2[idx] = *(const float4*)&B2[idx];
    }
    unsigned long long acc[8][4];
    #pragma unroll
    for (int i = 0; i < 8; i++)
        #pragma unroll
        for (int j = 0; j < 4; j++) acc[i][j] = 0ull;

    gemm_core(A, M, row0, Bs1, As, acc, tid, tx, ty);

    {
        float4 bA = *(const float4*)&b1[tx * 4];
        float4 bB = *(const float4*)&b1[64 + tx * 4];
        #pragma unroll
        for (int i = 0; i < 8; i++) {
            int r = ty * 8 + i;
            float2 f0 = unpk(acc[i][0]), f1 = unpk(acc[i][1]);
            float2 f2 = unpk(acc[i][2]), f3 = unpk(acc[i][3]);
            *(float4*)&Ts[r * PADT + tx * 4] =
                make_float4(lrelu(f0.x + bA.x), lrelu(f0.y + bA.y),
                            lrelu(f1.x + bA.z), lrelu(f1.y + bA.w));
            *(float4*)&Ts[r * PADT + 64 + tx * 4] =
                make_float4(lrelu(f2.x + bB.x), lrelu(f2.y + bB.y),
                            lrelu(f3.x + bB.z), lrelu(f3.y + bB.w));
        }
    }
    __syncthreads();

    #pragma unroll
    for (int i = 0; i < 8; i++)
        #pragma unroll
        for (int j = 0; j < 4; j++) acc[i][j] = 0ull;

    #pragma unroll 4
    for (int k = 0; k < 128; k++) {
        const float* br = &Bs2[k * 128];
        ulonglong2 b01 = *(const ulonglong2*)&br[tx * 4];
        ulonglong2 b23 = *(const ulonglong2*)&br[64 + tx * 4];
        #pragma unroll
        for (int i = 0; i < 8; i++) {
            unsigned long long as_ = splat2(Ts[(ty * 8 + i) * PADT + k]);
            fma2(acc[i][0], as_, b01.x);
            fma2(acc[i][1], as_, b01.y);
            fma2(acc[i][2], as_, b23.x);
            fma2(acc[i][3], as_, b23.y);
        }
    }

    float4 bA = *(const float4*)&b2[tx * 4];
    float4 bB = *(const float4*)&b2[64 + tx * 4];
    #pragma unroll
    for (int i = 0; i < 8; i++) {
        int grow = row0 + ty * 8 + i;
        if (grow >= M) continue;
        float2 f0 = unpk(acc[i][0]), f1 = unpk(acc[i][1]);
        float2 f2 = unpk(acc[i][2]), f3 = unpk(acc[i][3]);
        float4 r0 = *(const float4*)&X[(size_t)grow * 128 + tx * 4];
        float4 r1 = *(const float4*)&X[(size_t)grow * 128 + 64 + tx * 4];
        *(float4*)&O[(size_t)grow * 128 + tx * 4] =
            make_float4(f0.x + bA.x + r0.x, f0.y + bA.y + r0.y,
                        f1.x + bA.z + r0.z, f1.y + bA.w + r0.w);
        *(float4*)&O[(size_t)grow * 128 + 64 + tx * 4] =
            make_float4(f2.x + bB.x + r1.x, f2.y + bB.y + r1.y,
                        f3.x + bB.z + r1.z, f3.y + bB.w + r1.w);
    }
}

// ---------------- launch ----------------
extern "C" void kernel_launch(void* const* d_in, const int* in_sizes, int n_in,
                              void* d_out, int out_size) {
    const float* x   = (const float*)d_in[0];
    const float* pos = (const float*)d_in[1];
    const void*  ei  = d_in[2];
    const float* Wh1 = (const float*)d_in[3];
    const float* bh1 = (const float*)d_in[4];
    const float* Wh2 = (const float*)d_in[5];
    const float* bh2 = (const float*)d_in[6];
    const float* Wf  = (const float*)d_in[7];
    const float* bf  = (const float*)d_in[8];
    const float* Wg1 = (const float*)d_in[9];
    const float* bg1 = (const float*)d_in[10];
    const float* Wg2 = (const float*)d_in[11];
    const float* bg2 = (const float*)d_in[12];
    float* out = (float*)d_out;

    int M = in_sizes[0] / CDIM;   // 50000
    int E = in_sizes[2] / 2;      // 800000

    const int SM_BIAS   = (16384 + 16 * PADA) * sizeof(float);
    const int SM_HDELTA = (16384 + 16 * PADA + 384 + 128 * 3) * sizeof(float);
    const int SM_OUT    = (16384 * 2 + 128 * PADT + 16 * PADA) * sizeof(float);
    cudaFuncSetAttribute(gemm_bias_kernel,   cudaFuncAttributeMaxDynamicSharedMemorySize, SM_BIAS);
    cudaFuncSetAttribute(gemm_hdelta_kernel, cudaFuncAttributeMaxDynamicSharedMemorySize, SM_HDELTA);
    cudaFuncSetAttribute(gemm_out_kernel,    cudaFuncAttributeMaxDynamicSharedMemorySize, SM_OUT);

    float *xfp, *aggp;
    cudaGetSymbolAddress((void**)&xfp,  g_xf);
    cudaGetSymbolAddress((void**)&aggp, g_agg);

    int gemm_blocks = (M + 127) / 128;
    int eblocks = (E + 255) / 256;
    int nblocks = (M + 255) / 256;
    int sblocks = (M + 1023) / 1024;
    int wblocks = (M + 7) / 8;

    static cudaStream_t s_csr = nullptr, s_xf = nullptr;
    static cudaEvent_t  s_e0 = nullptr, s_e1 = nullptr, s_e2 = nullptr;
    if (s_csr == nullptr) {
        cudaStreamCreateWithFlags(&s_csr, cudaStreamNonBlocking);
        cudaStreamCreateWithFlags(&s_xf,  cudaStreamNonBlocking);
        cudaEventCreateWithFlags(&s_e0, cudaEventDisableTiming);
        cudaEventCreateWithFlags(&s_e1, cudaEventDisableTiming);
        cudaEventCreateWithFlags(&s_e2, cudaEventDisableTiming);
    }

    // fork point
    cudaEventRecord(s_e0, 0);
    cudaStreamWaitEvent(s_csr, s_e0, 0);
    cudaStreamWaitEvent(s_xf,  s_e0, 0);

    // branch 1 (s_csr): CSR build + payload pack
    detect_kernel<<<1, 32, 0, s_csr>>>((const unsigned int*)ei, E);
    zero_cnt_kernel<<<nblocks, 256, 0, s_csr>>>(M);
    convert_hist_kernel<<<eblocks, 256, 0, s_csr>>>(ei, E);
    scanA_kernel<<<sblocks, 1024, 0, s_csr>>>(M);
    scanB_kernel<<<1, 64, 0, s_csr>>>(sblocks);
    scanC_kernel<<<sblocks, 1024, 0, s_csr>>>(M);
    scatter_kernel<<<eblocks, 256, 0, s_csr>>>(pos, E);
    cudaEventRecord(s_e1, s_csr);

    // branch 2 (s_xf): xf GEMM — concurrent with hdelta on main
    gemm_bias_kernel<<<gemm_blocks, 256, SM_BIAS, s_xf>>>(x, Wf + 3 * 128, bf, xfp, M);
    cudaEventRecord(s_e2, s_xf);

    // main: hdelta GEMM
    gemm_hdelta_kernel<<<gemm_blocks, 256, SM_HDELTA>>>(x, Wh1, bh1, Wh2, bh2, M);

    // join, then aggregate + output MLP
    cudaStreamWaitEvent(0, s_e1, 0);
    cudaStreamWaitEvent(0, s_e2, 0);
    agg_kernel<<<wblocks, 256>>>(pos, Wf, M);
    gemm_out_kernel<<<gemm_blocks, 256, SM_OUT>>>(aggp, Wg1, bg1, Wg2, bg2, x, out, M);
}

// round 7
// speedup vs baseline: 1.2110x; 1.1076x over previous
#include <cuda_runtime.h>
#include <math.h>
#include <stdint.h>

#define NMAX 50000
#define EMAX 800000
#define CDIM 128
#define PADA 136   // transposed A-chunk row pad (floats)
#define PADT 132   // t-tile row pitch (floats)

// ---------------- device scratch ----------------
__device__ int   g_is64;
__device__ float g_xf [(size_t)NMAX * CDIM];
__device__ float g_agg[(size_t)NMAX * CDIM];
__device__ float g_delta[(size_t)NMAX * 3];
__device__ int   g_src [EMAX];
__device__ int   g_dst [EMAX];
__device__ int   g_esrc[EMAX];
__device__ int   g_cnt [NMAX];
__device__ int   g_cur [NMAX];
__device__ int   g_off [NMAX + 1];
__device__ int   g_bsum[64];
__device__ int   g_bpre[64];

// ---------------- f32x2 helpers ----------------
__device__ __forceinline__ unsigned long long splat2(float a) {
    unsigned long long r;
    asm("mov.b64 %0, {%1, %1};" : "=l"(r) : "f"(a));
    return r;
}
__device__ __forceinline__ void fma2(unsigned long long& d, unsigned long long a, unsigned long long b) {
    asm("fma.rn.f32x2 %0, %1, %2, %0;" : "+l"(d) : "l"(a), "l"(b));
}
__device__ __forceinline__ float2 unpk(unsigned long long v) {
    float lo, hi;
    asm("mov.b64 {%0, %1}, %2;" : "=f"(lo), "=f"(hi) : "l"(v));
    return make_float2(lo, hi);
}
__device__ __forceinline__ float lrelu(float v) { return (v > 0.f) ? v : 0.01f * v; }

// ---------------- dtype detection ----------------
__global__ void detect_kernel(const unsigned int* __restrict__ w, int E) {
    int nz = 0;
    int lim = 2 * E;
    for (int i = threadIdx.x; i < 256; i += 32) {
        int wi = 2 * i + 1;
        if (wi < lim) nz |= (w[wi] != 0u);
    }
    nz = __any_sync(0xffffffffu, nz);
    if (threadIdx.x == 0) g_is64 = nz ? 0 : 1;
}

__global__ void zero_cnt_kernel(int n) {
    int i = blockIdx.x * blockDim.x + threadIdx.x;
    if (i < n) { g_cnt[i] = 0; g_cur[i] = 0; }
}

__global__ void convert_hist_kernel(const void* __restrict__ ei, int E) {
    int i = blockIdx.x * blockDim.x + threadIdx.x;
    if (i >= E) return;
    int s, d;
    if (g_is64) {
        const long long* p = (const long long*)ei;
        s = (int)p[i];
        d = (int)p[E + i];
    } else {
        const int* p = (const int*)ei;
        s = p[i];
        d = p[E + i];
    }
    g_src[i] = s;
    g_dst[i] = d;
    atomicAdd(&g_cnt[d], 1);
}

// ---------------- hierarchical scan ----------------
__global__ void scanA_kernel(int n) {
    __shared__ int wsum[32];
    int tid = threadIdx.x, lane = tid & 31, wid = tid >> 5;
    int i = blockIdx.x * 1024 + tid;
    int v = (i < n) ? g_cnt[i] : 0;
    int x = v;
    #pragma unroll
    for (int d = 1; d < 32; d <<= 1) {
        int t = __shfl_up_sync(0xffffffffu, x, d);
        if (lane >= d) x += t;
    }
    if (lane == 31) wsum[wid] = x;
    __syncthreads();
    if (wid == 0) {
        int s = wsum[lane];
        #pragma unroll
        for (int d = 1; d < 32; d <<= 1) {
            int t = __shfl_up_sync(0xffffffffu, s, d);
            if (lane >= d) s += t;
        }
        wsum[lane] = s;
    }
    __syncthreads();
    if (wid > 0) x += wsum[wid - 1];
    if (i < n) g_off[i + 1] = x;
    if (tid == 1023) g_bsum[blockIdx.x] = x;
}

__global__ void scanB_kernel(int nb) {
    __shared__ int ws[2];
    int t = threadIdx.x, lane = t & 31, w = t >> 5;
    int v = (t < nb) ? g_bsum[t] : 0;
    int x = v;
    #pragma unroll
    for (int d = 1; d < 32; d <<= 1) {
        int u = __shfl_up_sync(0xffffffffu, x, d);
        if (lane >= d) x += u;
    }
    if (lane == 31) ws[w] = x;
    __syncthreads();
    if (w == 1) x += ws[0];
    if (t < nb) g_bpre[t] = x - v;
}

__global__ void scanC_kernel(int n) {
    int i = blockIdx.x * 1024 + threadIdx.x;
    int add = g_bpre[blockIdx.x];
    if (i < n) g_off[i + 1] += add;
    if (i == 0) g_off[0] = 0;
}

__global__ void scatter_kernel(int E) {
    int i = blockIdx.x * blockDim.x + threadIdx.x;
    if (i >= E) return;
    int d = g_dst[i];
    int p = g_off[d] + atomicAdd(&g_cur[d], 1);
    g_esrc[p] = g_src[i];
}

// ---------------- GEMM core with register-prefetch pipeline ----------------
__device__ __forceinline__ void gemm_core(
    const float* __restrict__ A, int M, int row0,
    const float* Bs, float* As, unsigned long long acc[8][4],
    int tid, int tx, int ty)
{
    int r_ = tid >> 2;
    int c_ = (tid & 3) * 4;
    int g0 = row0 + r_;
    int g1 = row0 + 64 + r_;
    const float* A0 = &A[(size_t)g0 * 128 + c_];
    const float* A1 = &A[(size_t)g1 * 128 + c_];
    bool ok0 = g0 < M, ok1 = g1 < M;

    float4 v0 = make_float4(0.f, 0.f, 0.f, 0.f);
    float4 v1 = make_float4(0.f, 0.f, 0.f, 0.f);
    if (ok0) v0 = *(const float4*)A0;
    if (ok1) v1 = *(const float4*)A1;

    #pragma unroll
    for (int k0 = 0; k0 < 128; k0 += 16) {
        As[(c_ + 0) * PADA + r_] = v0.x;
        As[(c_ + 1) * PADA + r_] = v0.y;
        As[(c_ + 2) * PADA + r_] = v0.z;
        As[(c_ + 3) * PADA + r_] = v0.w;
        As[(c_ + 0) * PADA + 64 + r_] = v1.x;
        As[(c_ + 1) * PADA + 64 + r_] = v1.y;
        As[(c_ + 2) * PADA + 64 + r_] = v1.z;
        As[(c_ + 3) * PADA + 64 + r_] = v1.w;
        if (k0 < 112) {
            v0 = make_float4(0.f, 0.f, 0.f, 0.f);
            v1 = make_float4(0.f, 0.f, 0.f, 0.f);
            if (ok0) v0 = *(const float4*)(A0 + k0 + 16);
            if (ok1) v1 = *(const float4*)(A1 + k0 + 16);
        }
        __syncthreads();
        #pragma unroll
        for (int k = 0; k < 16; k++) {
            float4 a0 = *(float4*)&As[k * PADA + ty * 8];
            float4 a1 = *(float4*)&As[k * PADA + ty * 8 + 4];
            const float* br = &Bs[(k0 + k) * 128];
            ulonglong2 b01 = *(const ulonglong2*)&br[tx * 4];
            ulonglong2 b23 = *(const ulonglong2*)&br[64 + tx * 4];
            float av[8] = {a0.x, a0.y, a0.z, a0.w, a1.x, a1.y, a1.z, a1.w};
            #pragma unroll
            for (int i = 0; i < 8; i++) {
                unsigned long long as_ = splat2(av[i]);
                fma2(acc[i][0], as_, b01.x);
                fma2(acc[i][1], as_, b01.y);
                fma2(acc[i][2], as_, b23.x);
                fma2(acc[i][3], as_, b23.y);
            }
        }
        __syncthreads();
    }
}

// ---------------- xf = x @ Wf_x + bf ----------------
__global__ __launch_bounds__(256, 2)
void gemm_bias_kernel(const float* __restrict__ A, const float* __restrict__ B,
                      const float* __restrict__ bias, float* __restrict__ O, int M) {
    extern __shared__ float sm[];
    float* Bs = sm;
    float* As = sm + 16384;
    int tid = threadIdx.x, tx = tid & 15, ty = tid >> 4;
    int row0 = blockIdx.x * 128;

    #pragma unroll
    for (int it = 0; it < 16; ++it) {
        int idx = (it * 256 + tid) * 4;
        *(float4*)&Bs[idx] = *(const float4*)&B[idx];
    }
    unsigned long long acc[8][4];
    #pragma unroll
    for (int i = 0; i < 8; i++)
        #pragma unroll
        for (int j = 0; j < 4; j++) acc[i][j] = 0ull;

    gemm_core(A, M, row0, Bs, As, acc, tid, tx, ty);

    float4 bA = *(const float4*)&bias[tx * 4];
    float4 bB = *(const float4*)&bias[64 + tx * 4];
    #pragma unroll
    for (int i = 0; i < 8; i++) {
        int grow = row0 + ty * 8 + i;
        if (grow >= M) continue;
        float2 f0 = unpk(acc[i][0]), f1 = unpk(acc[i][1]);
        float2 f2 = unpk(acc[i][2]), f3 = unpk(acc[i][3]);
        *(float4*)&O[(size_t)grow * 128 + tx * 4] =
            make_float4(f0.x + bA.x, f0.y + bA.y, f1.x + bA.z, f1.y + bA.w);
        *(float4*)&O[(size_t)grow * 128 + 64 + tx * 4] =
            make_float4(f2.x + bB.x, f2.y + bB.y, f3.x + bB.z, f3.y + bB.w);
    }
}

// ---------------- delta = tanh(lrelu(x@Wh1+bh1) @ Wh2 + bh2), fused ----------------
__global__ __launch_bounds__(256, 2)
void gemm_hdelta_kernel(const float* __restrict__ A, const float* __restrict__ B,
                        const float* __restrict__ bias,
                        const float* __restrict__ Wh2, const float* __restrict__ bh2, int M) {
    extern __shared__ float sm[];
    float* Bs   = sm;
    float* As   = sm + 16384;
    float* sW2  = sm + 16384 + 2176;
    float* sdel = sm + 16384 + 2176 + 384;
    int tid = threadIdx.x, tx = tid & 15, ty = tid >> 4;
    int row0 = blockIdx.x * 128;

    #pragma unroll
    for (int it = 0; it < 16; ++it) {
        int idx = (it * 256 + tid) * 4;
        *(float4*)&Bs[idx] = *(const float4*)&B[idx];
    }
    if (tid < 96) *(float4*)&sW2[tid * 4] = *(const float4*)&Wh2[tid * 4];

    unsigned long long acc[8][4];
    #pragma unroll
    for (int i = 0; i < 8; i++)
        #pragma unroll
        for (int j = 0; j < 4; j++) acc[i][j] = 0ull;

    gemm_core(A, M, row0, Bs, As, acc, tid, tx, ty);

    float4 bA = *(const float4*)&bias[tx * 4];
    float4 bB = *(const float4*)&bias[64 + tx * 4];
    float bb[8] = {bA.x, bA.y, bA.z, bA.w, bB.x, bB.y, bB.z, bB.w};

    #pragma unroll
    for (int i = 0; i < 8; i++) {
        float p0 = 0.f, p1 = 0.f, p2 = 0.f;
        #pragma unroll
        for (int j = 0; j < 4; j++) {
            int c0 = (j < 2) ? (tx * 4 + j * 2) : (64 + tx * 4 + (j - 2) * 2);
            float2 f = unpk(acc[i][j]);
            f.x = lrelu(f.x + bb[j * 2 + 0]);
            f.y = lrelu(f.y + bb[j * 2 + 1]);
            p0 += f.x * sW2[c0 * 3 + 0] + f.y * sW2[(c0 + 1) * 3 + 0];
            p1 += f.x * sW2[c0 * 3 + 1] + f.y * sW2[(c0 + 1) * 3 + 1];
            p2 += f.x * sW2[c0 * 3 + 2] + f.y * sW2[(c0 + 1) * 3 + 2];
        }
        #pragma unroll
        for (int d = 1; d < 16; d <<= 1) {
            p0 += __shfl_xor_sync(0xffffffffu, p0, d);
            p1 += __shfl_xor_sync(0xffffffffu, p1, d);
            p2 += __shfl_xor_sync(0xffffffffu, p2, d);
        }
        if (tx == 0) {
            int r = ty * 8 + i;
            sdel[r * 3 + 0] = p0;
            sdel[r * 3 + 1] = p1;
            sdel[r * 3 + 2] = p2;
        }
    }
    __syncthreads();
    if (tid < 128) {
        int grow = row0 + tid;
        if (grow < M) {
            g_delta[grow * 3 + 0] = tanhf(sdel[tid * 3 + 0] + bh2[0]);
            g_delta[grow * 3 + 1] = tanhf(sdel[tid * 3 + 1] + bh2[1]);
            g_delta[grow * 3 + 2] = tanhf(sdel[tid * 3 + 2] + bh2[2]);
        }
    }
}

// ---------------- edge aggregation: warp per dst node, unroll 4 ----------------
__global__ void agg_kernel(const float* __restrict__ pos, const float* __restrict__ Wf, int N) {
    int warp = (blockIdx.x * blockDim.x + threadIdx.x) >> 5;
    int lane = threadIdx.x & 31;
    if (warp >= N) return;
    int c = lane * 4;
    float4 w0 = *(const float4*)&Wf[c];
    float4 w1 = *(const float4*)&Wf[128 + c];
    float4 w2 = *(const float4*)&Wf[256 + c];
    float bx = g_delta[warp * 3 + 0] - pos[warp * 3 + 0];
    float by = g_delta[warp * 3 + 1] - pos[warp * 3 + 1];
    float bz = g_delta[warp * 3 + 2] - pos[warp * 3 + 2];
    int p0 = g_off[warp], p1 = g_off[warp + 1];
    float4 acc = make_float4(-INFINITY, -INFINITY, -INFINITY, -INFINITY);
    int p = p0;
    // unroll 4: batch index loads, then pos broadcasts, then xf gathers -> MLP~4
    for (; p + 4 <= p1; p += 4) {
        int s0 = g_esrc[p + 0];
        int s1 = g_esrc[p + 1];
        int s2 = g_esrc[p + 2];
        int s3 = g_esrc[p + 3];
        float rx0 = pos[s0 * 3 + 0] + bx, ry0 = pos[s0 * 3 + 1] + by, rz0 = pos[s0 * 3 + 2] + bz;
        float rx1 = pos[s1 * 3 + 0] + bx, ry1 = pos[s1 * 3 + 1] + by, rz1 = pos[s1 * 3 + 2] + bz;
        float rx2 = pos[s2 * 3 + 0] + bx, ry2 = pos[s2 * 3 + 1] + by, rz2 = pos[s2 * 3 + 2] + bz;
        float rx3 = pos[s3 * 3 + 0] + bx, ry3 = pos[s3 * 3 + 1] + by, rz3 = pos[s3 * 3 + 2] + bz;
        float4 v0 = *(const float4*)&g_xf[(size_t)s0 * 128 + c];
        float4 v1 = *(const float4*)&g_xf[(size_t)s1 * 128 + c];
        float4 v2 = *(const float4*)&g_xf[(size_t)s2 * 128 + c];
        float4 v3 = *(const float4*)&g_xf[(size_t)s3 * 128 + c];
        acc.x = fmaxf(acc.x, fmaf(rz0, w2.x, fmaf(ry0, w1.x, fmaf(rx0, w0.x, v0.x))));
        acc.y = fmaxf(acc.y, fmaf(rz0, w2.y, fmaf(ry0, w1.y, fmaf(rx0, w0.y, v0.y))));
        acc.z = fmaxf(acc.z, fmaf(rz0, w2.z, fmaf(ry0, w1.z, fmaf(rx0, w0.z, v0.z))));
        acc.w = fmaxf(acc.w, fmaf(rz0, w2.w, fmaf(ry0, w1.w, fmaf(rx0, w0.w, v0.w))));
        acc.x = fmaxf(acc.x, fmaf(rz1, w2.x, fmaf(ry1, w1.x, fmaf(rx1, w0.x, v1.x))));
        acc.y = fmaxf(acc.y, fmaf(rz1, w2.y, fmaf(ry1, w1.y, fmaf(rx1, w0.y, v1.y))));
        acc.z = fmaxf(acc.z, fmaf(rz1, w2.z, fmaf(ry1, w1.z, fmaf(rx1, w0.z, v1.z))));
        acc.w = fmaxf(acc.w, fmaf(rz1, w2.w, fmaf(ry1, w1.w, fmaf(rx1, w0.w, v1.w))));
        acc.x = fmaxf(acc.x, fmaf(rz2, w2.x, fmaf(ry2, w1.x, fmaf(rx2, w0.x, v2.x))));
        acc.y = fmaxf(acc.y, fmaf(rz2, w2.y, fmaf(ry2, w1.y, fmaf(rx2, w0.y, v2.y))));
        acc.z = fmaxf(acc.z, fmaf(rz2, w2.z, fmaf(ry2, w1.z, fmaf(rx2, w0.z, v2.z))));
        acc.w = fmaxf(acc.w, fmaf(rz2, w2.w, fmaf(ry2, w1.w, fmaf(rx2, w0.w, v2.w))));
        acc.x = fmaxf(acc.x, fmaf(rz3, w2.x, fmaf(ry3, w1.x, fmaf(rx3, w0.x, v3.x))));
        acc.y = fmaxf(acc.y, fmaf(rz3, w2.y, fmaf(ry3, w1.y, fmaf(rx3, w0.y, v3.y))));
        acc.z = fmaxf(acc.z, fmaf(rz3, w2.z, fmaf(ry3, w1.z, fmaf(rx3, w0.z, v3.z))));
        acc.w = fmaxf(acc.w, fmaf(rz3, w2.w, fmaf(ry3, w1.w, fmaf(rx3, w0.w, v3.w))));
    }
    for (; p < p1; ++p) {
        int s = g_esrc[p];
        float rx = pos[s * 3 + 0] + bx, ry = pos[s * 3 + 1] + by, rz = pos[s * 3 + 2] + bz;
        float4 v = *(const float4*)&g_xf[(size_t)s * 128 + c];
        acc.x = fmaxf(acc.x, fmaf(rz, w2.x, fmaf(ry, w1.x, fmaf(rx, w0.x, v.x))));
        acc.y = fmaxf(acc.y, fmaf(rz, w2.y, fmaf(ry, w1.y, fmaf(rx, w0.y, v.y))));
        acc.z = fmaxf(acc.z, fmaf(rz, w2.z, fmaf(ry, w1.z, fmaf(rx, w0.z, v.z))));
        acc.w = fmaxf(acc.w, fmaf(rz, w2.w, fmaf(ry, w1.w, fmaf(rx, w0.w, v.w))));
    }
    float4 o;
    if (p1 > p0) {
        o.x = lrelu(acc.x); o.y = lrelu(acc.y);
        o.z = lrelu(acc.z); o.w = lrelu(acc.w);
    } else {
        o = make_float4(0.f, 0.f, 0.f, 0.f);
    }
    *(float4*)&g_agg[(size_t)warp * 128 + c] = o;
}

// ---------------- fused: out = lrelu(agg@Wg1+bg1)@Wg2 + bg2 + x ----------------
__global__ __launch_bounds__(256, 1)
void gemm_out_kernel(const float* __restrict__ A, const float* __restrict__ B1,
                     const float* __restrict__ b1, const float* __restrict__ B2,
                     const float* __restrict__ b2, const float* __restrict__ X,
                     float* __restrict__ O, int M) {
    extern __shared__ float sm[];
    float* Bs1 = sm;
    float* Bs2 = sm + 16384;
    float* Ts  = sm + 32768;
    float* As  = sm + 32768 + 16896;
    int tid = threadIdx.x, tx = tid & 15, ty = tid >> 4;
    int row0 = blockIdx.x * 128;

    #pragma unroll
    for (int it = 0; it < 16; ++it) {
        int idx = (it * 256 + tid) * 4;
        *(float4*)&Bs1[idx] = *(const float4*)&B1[idx];
        *(float4*)&Bs2[idx] = *(const float4*)&B2[idx];
    }
    unsigned long long acc[8][4];
    #pragma unroll
    for (int i = 0; i < 8; i++)
        #pragma unroll
        for (int j = 0; j < 4; j++) acc[i][j] = 0ull;

    gemm_core(A, M, row0, Bs1, As, acc, tid, tx, ty);

    {
        float4 bA = *(const float4*)&b1[tx * 4];
        float4 bB = *(const float4*)&b1[64 + tx * 4];
        #pragma unroll
        for (int i = 0; i < 8; i++) {
            int r = ty * 8 + i;
            float2 f0 = unpk(acc[i][0]), f1 = unpk(acc[i][1]);
            float2 f2 = unpk(acc[i][2]), f3 = unpk(acc[i][3]);
            *(float4*)&Ts[r * PADT + tx * 4] =
                make_float4(lrelu(f0.x + bA.x), lrelu(f0.y + bA.y),
                            lrelu(f1.x + bA.z), lrelu(f1.y + bA.w));
            *(float4*)&Ts[r * PADT + 64 + tx * 4] =
                make_float4(lrelu(f2.x + bB.x), lrelu(f2.y + bB.y),
                            lrelu(f3.x + bB.z), lrelu(f3.y + bB.w));
        }
    }
    __syncthreads();

    #pragma unroll
    for (int i = 0; i < 8; i++)
        #pragma unroll
        for (int j = 0; j < 4; j++) acc[i][j] = 0ull;

    #pragma unroll 4
    for (int k = 0; k < 128; k++) {
        const float* br = &Bs2[k * 128];
        ulonglong2 b01 = *(const ulonglong2*)&br[tx * 4];
        ulonglong2 b23 = *(const ulonglong2*)&br[64 + tx * 4];
        #pragma unroll
        for (int i = 0; i < 8; i++) {
            unsigned long long as_ = splat2(Ts[(ty * 8 + i) * PADT + k]);
            fma2(acc[i][0], as_, b01.x);
            fma2(acc[i][1], as_, b01.y);
            fma2(acc[i][2], as_, b23.x);
            fma2(acc[i][3], as_, b23.y);
        }
    }

    float4 bA = *(const float4*)&b2[tx * 4];
    float4 bB = *(const float4*)&b2[64 + tx * 4];
    #pragma unroll
    for (int i = 0; i < 8; i++) {
        int grow = row0 + ty * 8 + i;
        if (grow >= M) continue;
        float2 f0 = unpk(acc[i][0]), f1 = unpk(acc[i][1]);
        float2 f2 = unpk(acc[i][2]), f3 = unpk(acc[i][3]);
        float4 r0 = *(const float4*)&X[(size_t)grow * 128 + tx * 4];
        float4 r1 = *(const float4*)&X[(size_t)grow * 128 + 64 + tx * 4];
        *(float4*)&O[(size_t)grow * 128 + tx * 4] =
            make_float4(f0.x + bA.x + r0.x, f0.y + bA.y + r0.y,
                        f1.x + bA.z + r0.z, f1.y + bA.w + r0.w);
        *(float4*)&O[(size_t)grow * 128 + 64 + tx * 4] =
            make_float4(f2.x + bB.x + r1.x, f2.y + bB.y + r1.y,
                        f3.x + bB.z + r1.z, f3.y + bB.w + r1.w);
    }
}

// ---------------- launch ----------------
extern "C" void kernel_launch(void* const* d_in, const int* in_sizes, int n_in,
                              void* d_out, int out_size) {
    const float* x   = (const float*)d_in[0];
    const float* pos = (const float*)d_in[1];
    const void*  ei  = d_in[2];
    const float* Wh1 = (const float*)d_in[3];
    const float* bh1 = (const float*)d_in[4];
    const float* Wh2 = (const float*)d_in[5];
    const float* bh2 = (const float*)d_in[6];
    const float* Wf  = (const float*)d_in[7];
    const float* bf  = (const float*)d_in[8];
    const float* Wg1 = (const float*)d_in[9];
    const float* bg1 = (const float*)d_in[10];
    const float* Wg2 = (const float*)d_in[11];
    const float* bg2 = (const float*)d_in[12];
    float* out = (float*)d_out;

    int M = in_sizes[0] / CDIM;   // 50000
    int E = in_sizes[2] / 2;      // 800000

    const int SM_BIAS   = (16384 + 16 * PADA) * sizeof(float);
    const int SM_HDELTA = (16384 + 16 * PADA + 384 + 128 * 3) * sizeof(float);
    const int SM_OUT    = (16384 * 2 + 128 * PADT + 16 * PADA) * sizeof(float);
    cudaFuncSetAttribute(gemm_bias_kernel,   cudaFuncAttributeMaxDynamicSharedMemorySize, SM_BIAS);
    cudaFuncSetAttribute(gemm_hdelta_kernel, cudaFuncAttributeMaxDynamicSharedMemorySize, SM_HDELTA);
    cudaFuncSetAttribute(gemm_out_kernel,    cudaFuncAttributeMaxDynamicSharedMemorySize, SM_OUT);

    float *xfp, *aggp;
    cudaGetSymbolAddress((void**)&xfp,  g_xf);
    cudaGetSymbolAddress((void**)&aggp, g_agg);

    int gemm_blocks = (M + 127) / 128;
    int eblocks = (E + 255) / 256;
    int nblocks = (M + 255) / 256;
    int sblocks = (M + 1023) / 1024;
    int wblocks = (M + 7) / 8;

    static cudaStream_t s_side = nullptr;
    static cudaEvent_t  s_e0 = nullptr, s_e1 = nullptr;
    if (s_side == nullptr) {
        cudaStreamCreateWithFlags(&s_side, cudaStreamNonBlocking);
        cudaEventCreateWithFlags(&s_e0, cudaEventDisableTiming);
        cudaEventCreateWithFlags(&s_e1, cudaEventDisableTiming);
    }

    // fork: CSR build on side stream
    cudaEventRecord(s_e0, 0);
    cudaStreamWaitEvent(s_side, s_e0, 0);
    detect_kernel<<<1, 32, 0, s_side>>>((const unsigned int*)ei, E);
    zero_cnt_kernel<<<nblocks, 256, 0, s_side>>>(M);
    convert_hist_kernel<<<eblocks, 256, 0, s_side>>>(ei, E);
    scanA_kernel<<<sblocks, 1024, 0, s_side>>>(M);
    scanB_kernel<<<1, 64, 0, s_side>>>(sblocks);
    scanC_kernel<<<sblocks, 1024, 0, s_side>>>(M);
    scatter_kernel<<<eblocks, 256, 0, s_side>>>(E);
    cudaEventRecord(s_e1, s_side);

    // main stream: node GEMMs (serial — R4 structure)
    gemm_hdelta_kernel<<<gemm_blocks, 256, SM_HDELTA>>>(x, Wh1, bh1, Wh2, bh2, M);
    gemm_bias_kernel<<<gemm_blocks, 256, SM_BIAS>>>(x, Wf + 3 * 128, bf, xfp, M);

    // join, then aggregate + output MLP
    cudaStreamWaitEvent(0, s_e1, 0);
    agg_kernel<<<wblocks, 256>>>(pos, Wf, M);
    gemm_out_kernel<<<gemm_blocks, 256, SM_OUT>>>(aggp, Wg1, bg1, Wg2, bg2, x, out, M);
}